// round 12
// baseline (speedup 1.0000x reference)
#include <cuda_runtime.h>
#include <math.h>

// Problem constants (fixed by setup_inputs)
#define BB    2
#define NN    2048
#define FIN   256
#define CC    64              // feature width of both layers (8 heads * 8 = 64, Fout = 64)
#define MM    (BB*NN)         // 4096 rows
#define EMAX  32768
#define CAP   64              // per-node adjacency bucket capacity (Poisson(16) -> safe)
#define WBS   (CAP+4)         // weight-buffer stride: bank = 4*l8+g, conflict-free
#define ALPHA 0.2f            // leaky_relu slope

// ---------------- scratch (device globals; no allocation allowed) ----------------
static __device__ __align__(16) float g_h1[MM*CC];
static __device__ __align__(16) float g_x1[MM*CC];
static __device__ __align__(16) float g_h2[MM*CC];
static __device__ __align__(16) float g_pre[MM*CC];
static __device__ float g_s1a[8*MM];
static __device__ float g_s2a[8*MM];
static __device__ float g_s1b[MM];
static __device__ float g_s2b[MM];
static __device__ float2 g_part[256*64];  // per-agg2-block (max,sum) column partials
static __device__ int g_deg[NN];        // zeros at load; re-zeroed by k_lsm each call
static __device__ int g_adj[NN*CAP];    // bucketed adjacency (targets), 512 KB

// ---------------- k_gemm1: 16x64 tile of h1 = x @ W1 (+ adj build + head scores) ----
// 256 blocks x 256 threads; thread = 1x4 micro tile. W repacked inline from W_h [8,256,8].
__global__ void k_gemm1(const float* __restrict__ x, const float* __restrict__ Wh,
                        const float* __restrict__ ah,
                        const int* __restrict__ edges, int E) {
    __shared__ float As[16][64];
    __shared__ float Ws[64][64];
    __shared__ float Cs[16][64];
    int tid = threadIdx.x;
    // adjacency build prologue: 256*256 = 65536 >= E
    int e = blockIdx.x * 256 + tid;
    if (e < E) {
        int s = edges[e], t = edges[E + e];
        int pos = atomicAdd(&g_deg[s], 1);
        if (pos < CAP) g_adj[s*CAP + pos] = t;
    }
    int tx = tid & 15;
    int ty = tid >> 4;
    int m0 = blockIdx.x * 16;
    float acc[4] = {};
    for (int k0 = 0; k0 < FIN; k0 += 64) {
        *reinterpret_cast<float4*>(&As[ty][tx*4]) =
            *reinterpret_cast<const float4*>(&x[(m0 + ty) * FIN + k0 + tx*4]);
        #pragma unroll
        for (int v = 0; v < 4; v++) {
            int idx = tid + v*256;
            int r = idx >> 4, c4 = idx & 15;
            int hh = c4 >> 1, o4 = (c4 & 1) * 4;   // W_h[h][f][o], 16B-aligned groups
            *reinterpret_cast<float4*>(&Ws[r][c4*4]) =
                *reinterpret_cast<const float4*>(&Wh[hh*(FIN*8) + (k0 + r)*8 + o4]);
        }
        __syncthreads();
        #pragma unroll 16
        for (int kk = 0; kk < 64; kk++) {
            float a0 = As[ty][kk];
            float4 b4 = *reinterpret_cast<const float4*>(&Ws[kk][tx*4]);
            acc[0] = fmaf(a0, b4.x, acc[0]);
            acc[1] = fmaf(a0, b4.y, acc[1]);
            acc[2] = fmaf(a0, b4.z, acc[2]);
            acc[3] = fmaf(a0, b4.w, acc[3]);
        }
        __syncthreads();
    }
    float4 o4 = make_float4(acc[0], acc[1], acc[2], acc[3]);
    *reinterpret_cast<float4*>(&g_h1[(m0 + ty) * CC + tx*4]) = o4;
    *reinterpret_cast<float4*>(&Cs[ty][tx*4]) = o4;
    __syncthreads();
    // head-score epilogue: thread (ty, tx<8) owns head tx of row m0+ty
    if (tx < 8) {
        int m = m0 + ty;
        float d1 = 0.f, d2 = 0.f;
        #pragma unroll
        for (int o = 0; o < 8; o++) {
            float v = Cs[ty][tx*8 + o];
            d1 = fmaf(v, ah[tx*16 + o],     d1);
            d2 = fmaf(v, ah[tx*16 + 8 + o], d2);
        }
        g_s1a[tx*MM + m] = d1;
        g_s2a[tx*MM + m] = d2;
    }
}

// ---------------- agg core: edge-softmax aggregation for one row (one warp) --------
// Score passes: GS = OW/2 lanes per head compute e/w in parallel -> smem.
// Gather: 4 groups x 8 lanes; group g handles edges g, g+4, ...; lane l8 owns
// features l8*8..+7 (2x float4 -> full 256B h row per group). Reduce: xor 8,16.
// Dedup: duplicates count once (dense-cell .set semantics) -> ts=-1, w=0.
// Result (bias added, optional ELU) written to dst[l8*8..+7] by g==0 lanes.
template<int HH, int OW, bool DOELU>
__device__ __forceinline__ void agg_core(int gw,
                                         const float* __restrict__ h,
                                         const float* __restrict__ s1,
                                         const float* __restrict__ s2,
                                         const float* __restrict__ bias,
                                         float* dst,
                                         int* ts, float* wbase) {
    const int GS = OW / 2;                 // 4 (layer1) / 32 (layer2)
    int lane = threadIdx.x & 31;
    int b    = gw >> 11;                   // / NN
    int src  = gw & (NN - 1);
    int g    = lane >> 3;
    int l8   = lane & 7;
    const int hh_s = (OW == 8) ? (lane >> 2) : 0;
    int d = g_deg[src]; if (d > CAP) d = CAP;
    float acc[8] = {};
    float sw = 0.f;
    if (d == 0) {
        // empty row -> uniform 1/N softmax -> column mean of h (rare path)
        const float* hb = h + b * NN * CC + l8 * 8;
        for (int n = g; n < NN; n += 4) {
            float4 p = *reinterpret_cast<const float4*>(hb + n*CC);
            float4 q = *reinterpret_cast<const float4*>(hb + n*CC + 4);
            acc[0]+=p.x; acc[1]+=p.y; acc[2]+=p.z; acc[3]+=p.w;
            acc[4]+=q.x; acc[5]+=q.y; acc[6]+=q.z; acc[7]+=q.w;
        }
    } else {
        for (int j = lane; j < d; j += 32) ts[j] = g_adj[src*CAP + j];
        __syncwarp();
        if (d <= 32) {
            // O(1) dedup: keep first occurrence (lowest index)
            int t0 = (lane < d) ? ts[lane] : (-(int)lane - 1);  // unique sentinels
            unsigned mset = __match_any_sync(0xffffffffu, t0);
            bool dup0 = (lane < d) && ((mset & ((1u << lane) - 1u)) != 0u);
            __syncwarp();
            if (dup0) ts[lane] = -1;
        } else {
            int  t0 = -1, t1 = -1;
            bool dup0 = false, dup1 = false;
            if (lane < d)      { t0 = ts[lane];      for (int i = 0; i < lane;      i++) dup0 |= (ts[i] == t0); }
            if (lane + 32 < d) { t1 = ts[lane + 32]; for (int i = 0; i < lane + 32; i++) dup1 |= (ts[i] == t1); }
            __syncwarp();
            if (dup0) ts[lane]      = -1;
            if (dup1) ts[lane + 32] = -1;
        }
        __syncwarp();
        float sv = s1[hh_s*MM + gw];
        const float* s2h = s2 + hh_s*MM + b*NN;
        float* wb = wbase + hh_s * WBS;
        // pass 1: e_j -> smem, subgroup max (dups excluded)
        float mx = -INFINITY;
        for (int j = (lane & (GS - 1)); j < d; j += GS) {
            int t = ts[j];
            int tt = t < 0 ? 0 : t;
            float e = sv + s2h[tt];
            e = e > 0.f ? e : ALPHA * e;
            wb[j] = e;
            if (t >= 0) mx = fmaxf(mx, e);
        }
        #pragma unroll
        for (int off = GS >> 1; off; off >>= 1)
            mx = fmaxf(mx, __shfl_xor_sync(0xffffffffu, mx, off));
        // pass 2: w_j = exp(e_j - mx), subgroup sum
        for (int j = (lane & (GS - 1)); j < d; j += GS) {
            float w = (ts[j] >= 0) ? __expf(wb[j] - mx) : 0.f;
            wb[j] = w;
            sw += w;
        }
        #pragma unroll
        for (int off = GS >> 1; off; off >>= 1)
            sw += __shfl_xor_sync(0xffffffffu, sw, off);
        __syncwarp();
        // gather: group g takes edges j = g, g+4, ...
        const float* hb = h + b * NN * CC + l8 * 8;
        const float* wme = wbase + (HH == 8 ? l8 : 0) * WBS;
        for (int j = g; j < d; j += 4) {
            int t = ts[j];
            int tt = t < 0 ? 0 : t;
            float w = wme[j];
            float4 p = *reinterpret_cast<const float4*>(hb + tt*CC);
            float4 q = *reinterpret_cast<const float4*>(hb + tt*CC + 4);
            acc[0] = fmaf(w, p.x, acc[0]); acc[1] = fmaf(w, p.y, acc[1]);
            acc[2] = fmaf(w, p.z, acc[2]); acc[3] = fmaf(w, p.w, acc[3]);
            acc[4] = fmaf(w, q.x, acc[4]); acc[5] = fmaf(w, q.y, acc[5]);
            acc[6] = fmaf(w, q.z, acc[6]); acc[7] = fmaf(w, q.w, acc[7]);
        }
        __syncwarp();
    }
    #pragma unroll
    for (int off = 8; off <= 16; off <<= 1)
        #pragma unroll
        for (int i = 0; i < 8; i++)
            acc[i] += __shfl_xor_sync(0xffffffffu, acc[i], off);
    float inv;
    if (d == 0)          inv = 1.0f / NN;
    else if (OW == 8)    inv = 1.0f / __shfl_sync(0xffffffffu, sw, 4*l8);
    else                 inv = 1.0f / sw;
    if (g == 0) {
        float4 bz0 = *reinterpret_cast<const float4*>(bias + l8*8);
        float4 bz1 = *reinterpret_cast<const float4*>(bias + l8*8 + 4);
        float z[8];
        z[0]=acc[0]*inv+bz0.x; z[1]=acc[1]*inv+bz0.y; z[2]=acc[2]*inv+bz0.z; z[3]=acc[3]*inv+bz0.w;
        z[4]=acc[4]*inv+bz1.x; z[5]=acc[5]*inv+bz1.y; z[6]=acc[6]*inv+bz1.z; z[7]=acc[7]*inv+bz1.w;
        if (DOELU) {
            #pragma unroll
            for (int i = 0; i < 8; i++) z[i] = z[i] > 0.f ? z[i] : expm1f(z[i]);
        }
        *reinterpret_cast<float4*>(dst + l8*8)     = make_float4(z[0], z[1], z[2], z[3]);
        *reinterpret_cast<float4*>(dst + l8*8 + 4) = make_float4(z[4], z[5], z[6], z[7]);
    }
}

// ---------------- k_agg1: layer-1 aggregation (+bias+ELU) -> g_x1 ----------------
__global__ void k_agg1(const float* __restrict__ bh) {
    __shared__ int   ts_all[8][CAP];
    __shared__ float w_all[8][8*WBS];
    int warp = threadIdx.x >> 5;
    int row  = blockIdx.x * 8 + warp;
    agg_core<8, 8, true>(row, g_h1, g_s1a, g_s2a, bh,
                         g_x1 + row*CC, ts_all[warp], w_all[warp]);
}

// ---------------- k_gemm2: h2 = x1 @ Wo (+ layer-2 scores) ----------------
__global__ void k_gemm2(const float* __restrict__ Wo, const float* __restrict__ ao) {
    __shared__ float As[16][64];
    __shared__ float Ws[64][64];
    __shared__ float Cs[16][64];
    int tid = threadIdx.x;
    int tx = tid & 15;
    int ty = tid >> 4;
    int m0 = blockIdx.x * 16;
    *reinterpret_cast<float4*>(&As[ty][tx*4]) =
        *reinterpret_cast<const float4*>(&g_x1[(m0 + ty) * CC + tx*4]);
    #pragma unroll
    for (int v = 0; v < 4; v++) {
        int idx = tid + v*256;
        int r = idx >> 4, c4 = idx & 15;
        *reinterpret_cast<float4*>(&Ws[r][c4*4]) =
            *reinterpret_cast<const float4*>(&Wo[r*64 + c4*4]);
    }
    __syncthreads();
    float acc[4] = {};
    #pragma unroll 16
    for (int kk = 0; kk < 64; kk++) {
        float a0 = As[ty][kk];
        float4 b4 = *reinterpret_cast<const float4*>(&Ws[kk][tx*4]);
        acc[0] = fmaf(a0, b4.x, acc[0]);
        acc[1] = fmaf(a0, b4.y, acc[1]);
        acc[2] = fmaf(a0, b4.z, acc[2]);
        acc[3] = fmaf(a0, b4.w, acc[3]);
    }
    float4 o4 = make_float4(acc[0], acc[1], acc[2], acc[3]);
    *reinterpret_cast<float4*>(&g_h2[(m0 + ty) * CC + tx*4]) = o4;
    *reinterpret_cast<float4*>(&Cs[ty][tx*4]) = o4;
    __syncthreads();
    // layer-2 scores: 16 threads per row, 4 cols each, shfl-reduce over 16-lane groups
    float d1 = 0.f, d2 = 0.f;
    #pragma unroll
    for (int o = 0; o < 4; o++) {
        float v = Cs[ty][tx*4 + o];
        d1 = fmaf(v, ao[tx*4 + o],      d1);
        d2 = fmaf(v, ao[64 + tx*4 + o], d2);
    }
    #pragma unroll
    for (int off = 8; off; off >>= 1) {
        d1 += __shfl_down_sync(0xffffffffu, d1, off, 16);
        d2 += __shfl_down_sync(0xffffffffu, d2, off, 16);
    }
    if (tx == 0) { g_s1b[m0 + ty] = d1; g_s2b[m0 + ty] = d2; }
}

// ---------------- k_agg2: layer-2 aggregation (+bias) -> g_pre + lsm partials -------
// 256 blocks x 512 threads; warp per row (16 rows/block). Epilogue: per-block online
// (max,sum) partials per column over its 16 rows -> g_part[block][64].
__global__ void k_agg2(const float* __restrict__ bo) {
    __shared__ int   ts_all[16][CAP];
    __shared__ float w_all[16][WBS];
    __shared__ __align__(16) float zrow[16][64];
    int tid  = threadIdx.x;
    int warp = tid >> 5;
    int lane = tid & 31;
    int row  = blockIdx.x * 16 + warp;
    agg_core<1, 64, false>(row, g_h2, g_s1b, g_s2b, bo,
                           zrow[warp], ts_all[warp], w_all[warp]);
    __syncwarp();
    // copy this row from smem to g_pre (16 lanes x float4)
    if (lane < 16)
        *reinterpret_cast<float4*>(&g_pre[row*CC + lane*4]) =
            *reinterpret_cast<const float4*>(&zrow[warp][lane*4]);
    __syncthreads();
    // online (max,sum) per column over the 16 rows (conflict-free: row-major reads)
    if (tid < 64) {
        float m = -INFINITY, s = 0.f;
        #pragma unroll
        for (int r = 0; r < 16; r++) {
            float v = zrow[r][tid];
            float mn = fmaxf(m, v);
            s = s * __expf(m - mn) + __expf(v - mn);
            m = mn;
        }
        g_part[blockIdx.x*64 + tid] = make_float2(m, s);
    }
}

// ---------------- k_lsm: merge partials -> L, subtract, write out, deg re-zero ------
// 128 blocks x 256 threads; block j handles rows j*32..+32 (single batch each).
__global__ void k_lsm(float* __restrict__ out) {
    __shared__ float2 pm[4][64];
    __shared__ float Ls[64];
    int j = blockIdx.x;
    int t = threadIdx.x;
    int gt = j * 256 + t;
    if (gt < NN) g_deg[gt] = 0;          // restore invariant for next call
    int b = j >> 6;
    // merge this batch's 128 partials: thread (col = t&63, quarter q = t>>6) does 32
    int col = t & 63, q = t >> 6;
    const float2* base = g_part + b * 128 * 64;
    float m = -INFINITY, s = 0.f;
    for (int i = 0; i < 32; i++) {
        float2 ps = base[(q*32 + i)*64 + col];   // coalesced: 64 consecutive float2
        float mn = fmaxf(m, ps.x);
        s = s * __expf(m - mn) + ps.y * __expf(ps.x - mn);
        m = mn;
    }
    pm[q][col] = make_float2(m, s);
    __syncthreads();
    if (t < 64) {
        float2 a = pm[0][t];
        #pragma unroll
        for (int qq = 1; qq < 4; qq++) {
            float2 c = pm[qq][t];
            float mn = fmaxf(a.x, c.x);
            a.y = a.y * __expf(a.x - mn) + c.y * __expf(c.x - mn);
            a.x = mn;
        }
        Ls[t] = a.x + logf(a.y);
    }
    __syncthreads();
    // subtract + write: 2 passes x 16 rows, float4 coalesced
    int ty = t >> 4, c4 = t & 15;
    #pragma unroll
    for (int ps = 0; ps < 2; ps++) {
        int row = j*32 + ps*16 + ty;
        float4 v = *reinterpret_cast<const float4*>(&g_pre[row*CC + c4*4]);
        v.x -= Ls[c4*4];     v.y -= Ls[c4*4 + 1];
        v.z -= Ls[c4*4 + 2]; v.w -= Ls[c4*4 + 3];
        *reinterpret_cast<float4*>(&out[row*CC + c4*4]) = v;
    }
}

// ---------------- launch: 5 kernels ----------------
extern "C" void kernel_launch(void* const* d_in, const int* in_sizes, int n_in,
                              void* d_out, int out_size) {
    const float* x     = (const float*)d_in[0];
    const int*   edges = (const int*)  d_in[1];
    const float* Wh    = (const float*)d_in[2];
    const float* ah    = (const float*)d_in[3];
    const float* bh    = (const float*)d_in[4];
    const float* Wo    = (const float*)d_in[5];
    const float* ao    = (const float*)d_in[6];
    const float* bo    = (const float*)d_in[7];
    float* out = (float*)d_out;
    int E = in_sizes[1] / 2;
    if (E > EMAX) E = EMAX;   // defensive clamp; dataset uses E = 32768

    k_gemm1<<<MM/16, 256>>>(x, Wh, ah, edges, E);  // + adjacency build prologue
    k_agg1 <<<MM/8,  256>>>(bh);
    k_gemm2<<<MM/16, 256>>>(Wo, ao);
    k_agg2 <<<MM/16, 512>>>(bo);                   // + lsm column partials
    k_lsm  <<<MM/32, 256>>>(out);                  // merge + subtract + deg re-zero
}

// round 13
// speedup vs baseline: 1.1544x; 1.1544x over previous
#include <cuda_runtime.h>
#include <math.h>

// Problem constants (fixed by setup_inputs)
#define BB    2
#define NN    2048
#define FIN   256
#define CC    64              // feature width of both layers (8 heads * 8 = 64, Fout = 64)
#define MM    (BB*NN)         // 4096 rows
#define EMAX  32768
#define CAP   64              // per-node adjacency bucket capacity (Poisson(16) -> safe)
#define WBS   (CAP+4)         // weight-buffer stride: bank = 4*l8+g, conflict-free
#define ALPHA 0.2f            // leaky_relu slope

// ---------------- scratch (device globals; no allocation allowed) ----------------
static __device__ __align__(16) float g_h1[MM*CC];
static __device__ __align__(16) float g_x1[MM*CC];
static __device__ __align__(16) float g_h2[MM*CC];
static __device__ __align__(16) float g_pre[MM*CC];
static __device__ float g_s1a[8*MM];
static __device__ float g_s2a[8*MM];
static __device__ float g_s1b[MM];
static __device__ float g_s2b[MM];
static __device__ float2 g_part[256*64];  // per-agg2-block (max,sum) column partials
static __device__ int g_deg[NN];        // zeros at load; re-zeroed by k_lsm each call
static __device__ int g_adj[NN*CAP];    // bucketed adjacency (targets), 512 KB

// ---------------- GEMM body (R7-proven): C[32 x 64] = A[32 x K] * W[K x 64] ---------
// 128 blocks x 256 threads; thread = 2x4 micro tile. All staging via float4.
// LAYER==1: K=256, W repacked inline from W_h [8,256,8]; LAYER==2: K=64, W = W_o.
template<int LAYER>
__device__ __forceinline__ void gemm_body(const float* __restrict__ A,
                                          const float* __restrict__ Wraw,
                                          const float* __restrict__ avec,
                                          float* __restrict__ C,
                                          float* __restrict__ s1,
                                          float* __restrict__ s2) {
    const int K = (LAYER == 1) ? FIN : CC;
    __shared__ float As[32][64];
    __shared__ float Ws[64][64];
    __shared__ float Cs[32][64];
    int tid = threadIdx.x;
    int tx = tid & 15;        // col group (4 cols)
    int ty = tid >> 4;        // row group (2 rows)
    int m0 = blockIdx.x * 32;
    float acc[2][4] = {};
    for (int k0 = 0; k0 < K; k0 += 64) {
        // stage A tile: 512 float4, 2 per thread
        #pragma unroll
        for (int v = 0; v < 2; v++) {
            int idx = tid + v*256;            // 0..511
            int r = idx >> 4, c4 = idx & 15;
            *reinterpret_cast<float4*>(&As[r][c4*4]) =
                *reinterpret_cast<const float4*>(&A[(m0 + r) * K + k0 + c4*4]);
        }
        // stage W tile: 1024 float4, 4 per thread
        #pragma unroll
        for (int v = 0; v < 4; v++) {
            int idx = tid + v*256;            // 0..1023
            int r = idx >> 4, c4 = idx & 15;
            float4 w4;
            if (LAYER == 1) {
                int hh = c4 >> 1, o4 = (c4 & 1) * 4;   // W_h[h][f][o], 16B-aligned groups
                w4 = *reinterpret_cast<const float4*>(&Wraw[hh*(FIN*8) + (k0 + r)*8 + o4]);
            } else {
                w4 = *reinterpret_cast<const float4*>(&Wraw[(k0 + r)*64 + c4*4]);
            }
            *reinterpret_cast<float4*>(&Ws[r][c4*4]) = w4;
        }
        __syncthreads();
        #pragma unroll 8
        for (int kk = 0; kk < 64; kk++) {
            float a0 = As[ty*2    ][kk];
            float a1 = As[ty*2 + 1][kk];
            float4 b4 = *reinterpret_cast<const float4*>(&Ws[kk][tx*4]);
            float b[4] = {b4.x, b4.y, b4.z, b4.w};
            #pragma unroll
            for (int j = 0; j < 4; j++) {
                acc[0][j] = fmaf(a0, b[j], acc[0][j]);
                acc[1][j] = fmaf(a1, b[j], acc[1][j]);
            }
        }
        __syncthreads();
    }
    #pragma unroll
    for (int i = 0; i < 2; i++) {
        float4 o4 = make_float4(acc[i][0], acc[i][1], acc[i][2], acc[i][3]);
        *reinterpret_cast<float4*>(&C[(m0 + ty*2 + i) * CC + tx*4]) = o4;
        *reinterpret_cast<float4*>(&Cs[ty*2 + i][tx*4]) = o4;
    }
    __syncthreads();
    // score epilogue: 8 threads per row
    int r = tid >> 3;        // row 0..31
    int q = tid & 7;         // 0..7
    int m = m0 + r;
    if (LAYER == 1) {
        float d1 = 0.f, d2 = 0.f;
        #pragma unroll
        for (int o = 0; o < 8; o++) {
            float v = Cs[r][q*8 + o];
            d1 = fmaf(v, avec[q*16 + o],     d1);
            d2 = fmaf(v, avec[q*16 + 8 + o], d2);
        }
        s1[q*MM + m] = d1;
        s2[q*MM + m] = d2;
    } else {
        float d1 = 0.f, d2 = 0.f;
        #pragma unroll
        for (int o = 0; o < 8; o++) {
            float v = Cs[r][q*8 + o];
            d1 = fmaf(v, avec[q*8 + o],      d1);
            d2 = fmaf(v, avec[64 + q*8 + o], d2);
        }
        #pragma unroll
        for (int off = 4; off; off >>= 1) {
            d1 += __shfl_down_sync(0xffffffffu, d1, off, 8);
            d2 += __shfl_down_sync(0xffffffffu, d2, off, 8);
        }
        if (q == 0) { s1[m] = d1; s2[m] = d2; }
    }
}

// gemm1 also builds the bucketed adjacency as a prologue (128*256 = 32768 >= E)
__global__ void k_gemm1(const float* __restrict__ x, const float* __restrict__ Wh,
                        const float* __restrict__ ah,
                        const int* __restrict__ edges, int E) {
    int e = blockIdx.x * blockDim.x + threadIdx.x;
    if (e < E) {
        int s = edges[e];
        int t = edges[E + e];
        int pos = atomicAdd(&g_deg[s], 1);
        if (pos < CAP) g_adj[s*CAP + pos] = t;
    }
    gemm_body<1>(x, Wh, ah, g_h1, g_s1a, g_s2a);
}
__global__ void k_gemm2(const float* __restrict__ Wo, const float* __restrict__ ao) {
    gemm_body<2>(g_x1, Wo, ao, g_h2, g_s1b, g_s2b);
}

// ---------------- agg core: edge-softmax aggregation for one row (one warp) --------
// Score passes: GS = OW/2 lanes per head compute e/w in parallel -> smem.
// Gather: 4 groups x 8 lanes; group g handles edges g, g+4, ...; lane l8 owns
// features l8*8..+7 (2x float4 -> full 256B h row per group). Reduce: xor 8,16.
// Dedup: duplicates count once (dense-cell .set semantics) -> ts=-1, w=0.
// Result (bias added, optional ELU) written to dst[l8*8..+7] by g==0 lanes.
template<int HH, int OW, bool DOELU>
__device__ __forceinline__ void agg_core(int gw,
                                         const float* __restrict__ h,
                                         const float* __restrict__ s1,
                                         const float* __restrict__ s2,
                                         const float* __restrict__ bias,
                                         float* dst,
                                         int* ts, float* wbase) {
    const int GS = OW / 2;                 // 4 (layer1) / 32 (layer2)
    int lane = threadIdx.x & 31;
    int b    = gw >> 11;                   // / NN
    int src  = gw & (NN - 1);
    int g    = lane >> 3;
    int l8   = lane & 7;
    const int hh_s = (OW == 8) ? (lane >> 2) : 0;
    int d = g_deg[src]; if (d > CAP) d = CAP;
    float acc[8] = {};
    float sw = 0.f;
    if (d == 0) {
        // empty row -> uniform 1/N softmax -> column mean of h (rare path)
        const float* hb = h + b * NN * CC + l8 * 8;
        for (int n = g; n < NN; n += 4) {
            float4 p = *reinterpret_cast<const float4*>(hb + n*CC);
            float4 q = *reinterpret_cast<const float4*>(hb + n*CC + 4);
            acc[0]+=p.x; acc[1]+=p.y; acc[2]+=p.z; acc[3]+=p.w;
            acc[4]+=q.x; acc[5]+=q.y; acc[6]+=q.z; acc[7]+=q.w;
        }
    } else {
        for (int j = lane; j < d; j += 32) ts[j] = g_adj[src*CAP + j];
        __syncwarp();
        if (d <= 32) {
            // O(1) dedup: keep first occurrence (lowest index)
            int t0 = (lane < d) ? ts[lane] : (-(int)lane - 1);  // unique sentinels
            unsigned mset = __match_any_sync(0xffffffffu, t0);
            bool dup0 = (lane < d) && ((mset & ((1u << lane) - 1u)) != 0u);
            __syncwarp();
            if (dup0) ts[lane] = -1;
        } else {
            int  t0 = -1, t1 = -1;
            bool dup0 = false, dup1 = false;
            if (lane < d)      { t0 = ts[lane];      for (int i = 0; i < lane;      i++) dup0 |= (ts[i] == t0); }
            if (lane + 32 < d) { t1 = ts[lane + 32]; for (int i = 0; i < lane + 32; i++) dup1 |= (ts[i] == t1); }
            __syncwarp();
            if (dup0) ts[lane]      = -1;
            if (dup1) ts[lane + 32] = -1;
        }
        __syncwarp();
        float sv = s1[hh_s*MM + gw];
        const float* s2h = s2 + hh_s*MM + b*NN;
        float* wb = wbase + hh_s * WBS;
        // pass 1: e_j -> smem, subgroup max (dups excluded)
        float mx = -INFINITY;
        for (int j = (lane & (GS - 1)); j < d; j += GS) {
            int t = ts[j];
            int tt = t < 0 ? 0 : t;
            float e = sv + s2h[tt];
            e = e > 0.f ? e : ALPHA * e;
            wb[j] = e;
            if (t >= 0) mx = fmaxf(mx, e);
        }
        #pragma unroll
        for (int off = GS >> 1; off; off >>= 1)
            mx = fmaxf(mx, __shfl_xor_sync(0xffffffffu, mx, off));
        // pass 2: w_j = exp(e_j - mx), subgroup sum
        for (int j = (lane & (GS - 1)); j < d; j += GS) {
            float w = (ts[j] >= 0) ? __expf(wb[j] - mx) : 0.f;
            wb[j] = w;
            sw += w;
        }
        #pragma unroll
        for (int off = GS >> 1; off; off >>= 1)
            sw += __shfl_xor_sync(0xffffffffu, sw, off);
        __syncwarp();
        // gather: group g takes edges j = g, g+4, ...
        const float* hb = h + b * NN * CC + l8 * 8;
        const float* wme = wbase + (HH == 8 ? l8 : 0) * WBS;
        #pragma unroll 2
        for (int j = g; j < d; j += 4) {
            int t = ts[j];
            int tt = t < 0 ? 0 : t;
            float w = wme[j];
            float4 p = *reinterpret_cast<const float4*>(hb + tt*CC);
            float4 q = *reinterpret_cast<const float4*>(hb + tt*CC + 4);
            acc[0] = fmaf(w, p.x, acc[0]); acc[1] = fmaf(w, p.y, acc[1]);
            acc[2] = fmaf(w, p.z, acc[2]); acc[3] = fmaf(w, p.w, acc[3]);
            acc[4] = fmaf(w, q.x, acc[4]); acc[5] = fmaf(w, q.y, acc[5]);
            acc[6] = fmaf(w, q.z, acc[6]); acc[7] = fmaf(w, q.w, acc[7]);
        }
        __syncwarp();
    }
    #pragma unroll
    for (int off = 8; off <= 16; off <<= 1)
        #pragma unroll
        for (int i = 0; i < 8; i++)
            acc[i] += __shfl_xor_sync(0xffffffffu, acc[i], off);
    float inv;
    if (d == 0)          inv = 1.0f / NN;
    else if (OW == 8)    inv = 1.0f / __shfl_sync(0xffffffffu, sw, 4*l8);
    else                 inv = 1.0f / sw;
    if (g == 0) {
        float4 bz0 = *reinterpret_cast<const float4*>(bias + l8*8);
        float4 bz1 = *reinterpret_cast<const float4*>(bias + l8*8 + 4);
        float z[8];
        z[0]=acc[0]*inv+bz0.x; z[1]=acc[1]*inv+bz0.y; z[2]=acc[2]*inv+bz0.z; z[3]=acc[3]*inv+bz0.w;
        z[4]=acc[4]*inv+bz1.x; z[5]=acc[5]*inv+bz1.y; z[6]=acc[6]*inv+bz1.z; z[7]=acc[7]*inv+bz1.w;
        if (DOELU) {
            #pragma unroll
            for (int i = 0; i < 8; i++) z[i] = z[i] > 0.f ? z[i] : expm1f(z[i]);
        }
        *reinterpret_cast<float4*>(dst + l8*8)     = make_float4(z[0], z[1], z[2], z[3]);
        *reinterpret_cast<float4*>(dst + l8*8 + 4) = make_float4(z[4], z[5], z[6], z[7]);
    }
}

// ---------------- k_agg1: layer-1 aggregation (+bias+ELU) -> g_x1 ----------------
__global__ void k_agg1(const float* __restrict__ bh) {
    __shared__ int   ts_all[8][CAP];
    __shared__ float w_all[8][8*WBS];
    int warp = threadIdx.x >> 5;
    int row  = blockIdx.x * 8 + warp;
    agg_core<8, 8, true>(row, g_h1, g_s1a, g_s2a, bh,
                         g_x1 + row*CC, ts_all[warp], w_all[warp]);
}

// ---------------- k_agg2: layer-2 aggregation (+bias) -> g_pre + lsm partials -------
// 256 blocks x 512 threads; warp per row (16 rows/block). Epilogue: per-block online
// (max,sum) partials per column over its 16 rows -> g_part[block][64].
__global__ void k_agg2(const float* __restrict__ bo) {
    __shared__ int   ts_all[16][CAP];
    __shared__ float w_all[16][WBS];
    __shared__ __align__(16) float zrow[16][64];
    int tid  = threadIdx.x;
    int warp = tid >> 5;
    int lane = tid & 31;
    int row  = blockIdx.x * 16 + warp;
    agg_core<1, 64, false>(row, g_h2, g_s1b, g_s2b, bo,
                           zrow[warp], ts_all[warp], w_all[warp]);
    __syncwarp();
    // copy this row from smem to g_pre (16 lanes x float4)
    if (lane < 16)
        *reinterpret_cast<float4*>(&g_pre[row*CC + lane*4]) =
            *reinterpret_cast<const float4*>(&zrow[warp][lane*4]);
    __syncthreads();
    // online (max,sum) per column over the 16 rows (conflict-free: row-major reads)
    if (tid < 64) {
        float m = -INFINITY, s = 0.f;
        #pragma unroll
        for (int r = 0; r < 16; r++) {
            float v = zrow[r][tid];
            float mn = fmaxf(m, v);
            s = s * __expf(m - mn) + __expf(v - mn);
            m = mn;
        }
        g_part[blockIdx.x*64 + tid] = make_float2(m, s);
    }
}

// ---------------- k_lsm: merge partials -> L, subtract, write out, deg re-zero ------
// 128 blocks x 256 threads; block j handles rows j*32..+32 (single batch each).
__global__ void k_lsm(float* __restrict__ out) {
    __shared__ float2 pm[4][64];
    __shared__ float Ls[64];
    int j = blockIdx.x;
    int t = threadIdx.x;
    int gt = j * 256 + t;
    if (gt < NN) g_deg[gt] = 0;          // restore invariant for next call
    int b = j >> 6;
    // merge this batch's 128 partials: thread (col = t&63, quarter q = t>>6) does 32
    int col = t & 63, q = t >> 6;
    const float2* base = g_part + b * 128 * 64;
    float m = -INFINITY, s = 0.f;
    for (int i = 0; i < 32; i++) {
        float2 ps = base[(q*32 + i)*64 + col];   // coalesced: 64 consecutive float2
        float mn = fmaxf(m, ps.x);
        s = s * __expf(m - mn) + ps.y * __expf(ps.x - mn);
        m = mn;
    }
    pm[q][col] = make_float2(m, s);
    __syncthreads();
    if (t < 64) {
        float2 a = pm[0][t];
        #pragma unroll
        for (int qq = 1; qq < 4; qq++) {
            float2 c = pm[qq][t];
            float mn = fmaxf(a.x, c.x);
            a.y = a.y * __expf(a.x - mn) + c.y * __expf(c.x - mn);
            a.x = mn;
        }
        Ls[t] = a.x + logf(a.y);
    }
    __syncthreads();
    // subtract + write: 2 passes x 16 rows, float4 coalesced
    int ty = t >> 4, c4 = t & 15;
    #pragma unroll
    for (int ps = 0; ps < 2; ps++) {
        int row = j*32 + ps*16 + ty;
        float4 v = *reinterpret_cast<const float4*>(&g_pre[row*CC + c4*4]);
        v.x -= Ls[c4*4];     v.y -= Ls[c4*4 + 1];
        v.z -= Ls[c4*4 + 2]; v.w -= Ls[c4*4 + 3];
        *reinterpret_cast<float4*>(&out[row*CC + c4*4]) = v;
    }
}

// ---------------- launch: 5 kernels ----------------
extern "C" void kernel_launch(void* const* d_in, const int* in_sizes, int n_in,
                              void* d_out, int out_size) {
    const float* x     = (const float*)d_in[0];
    const int*   edges = (const int*)  d_in[1];
    const float* Wh    = (const float*)d_in[2];
    const float* ah    = (const float*)d_in[3];
    const float* bh    = (const float*)d_in[4];
    const float* Wo    = (const float*)d_in[5];
    const float* ao    = (const float*)d_in[6];
    const float* bo    = (const float*)d_in[7];
    float* out = (float*)d_out;
    int E = in_sizes[1] / 2;
    if (E > EMAX) E = EMAX;   // defensive clamp; dataset uses E = 32768

    k_gemm1<<<MM/32, 256>>>(x, Wh, ah, edges, E);  // + adjacency build prologue
    k_agg1 <<<MM/8,  256>>>(bh);
    k_gemm2<<<MM/32, 256>>>(Wo, ao);
    k_agg2 <<<MM/16, 512>>>(bo);                   // + lsm column partials
    k_lsm  <<<MM/32, 256>>>(out);                  // merge + subtract + deg re-zero
}